// round 2
// baseline (speedup 1.0000x reference)
#include <cuda_runtime.h>
#include <cstdint>

// Problem constants
#define BB      1024
#define CC      20
#define NT      26
#define VDIM    128
#define NSPL    10
#define NWORDS  100000

static const long long D_ELEMS = (long long)NSPL * NWORDS * VDIM;  // 128,000,000
#define COPY_BLOCKS 4736
#define THREADS 256

__global__ void __launch_bounds__(THREADS)
dmspline_fused(const float* __restrict__ x_vals,
               const int*   __restrict__ knot_ids,
               const int*   __restrict__ ctx,
               const int*   __restrict__ tids,
               const float* __restrict__ D,
               const float* __restrict__ W,
               const float* __restrict__ O,
               float* __restrict__ out_scores,   // B*NT floats at d_out
               float* __restrict__ out_D)        // D copy at d_out + B*NT
{
    int blk = blockIdx.x;

    if (blk >= BB) {
        // ---- D pass-through copy (vectorized, grid-stride) ----
        const float4* __restrict__ src = (const float4*)D;
        float4*       __restrict__ dst = (float4*)out_D;
        const long long n4     = D_ELEMS / 4;                       // 32M float4
        const long long stride = (long long)COPY_BLOCKS * THREADS;
        for (long long i = (long long)(blk - BB) * THREADS + threadIdx.x;
             i < n4; i += stride) {
            dst[i] = src[i];
        }
        return;
    }

    // ---- compute block: one batch row b ----
    const int b   = blk;
    const int tid = threadIdx.x;

    __shared__ float xs[VDIM];
    __shared__ int   ctx_s[CC];

    if (tid < CC) ctx_s[tid] = ctx[b * CC + tid];
    __syncthreads();

    if (tid < VDIM) {
        const float* __restrict__ Dk = D + (long long)knot_ids[b] * NWORDS * VDIM;
        float accD = 0.f, accW = 0.f;
        #pragma unroll
        for (int c = 0; c < CC; ++c) {
            const long long w = ctx_s[c];
            accD += Dk[w * VDIM + tid];
            accW += W [w * VDIM + tid];
        }
        xs[tid] = (accD * x_vals[b] + accW) * (1.0f / CC);
    }
    __syncthreads();

    // ---- scores: warp per target index ----
    const int warp = tid >> 5;
    const int lane = tid & 31;
    for (int n = warp; n < NT; n += (THREADS / 32)) {
        const long long t = tids[b * NT + n];
        float s = 0.f;
        #pragma unroll
        for (int i = 0; i < 4; ++i) {
            const int v = lane + 32 * i;
            s += xs[v] * O[(long long)v * NWORDS + t];
        }
        #pragma unroll
        for (int off = 16; off; off >>= 1)
            s += __shfl_down_sync(0xffffffffu, s, off);
        if (lane == 0) out_scores[b * NT + n] = s;
    }
}

extern "C" void kernel_launch(void* const* d_in, const int* in_sizes, int n_in,
                              void* d_out, int out_size)
{
    const float* x_vals = (const float*)d_in[0];
    const int*   knots  = (const int*)  d_in[1];
    const int*   ctx    = (const int*)  d_in[2];
    const int*   tids   = (const int*)  d_in[3];
    const float* D      = (const float*)d_in[4];
    const float* W      = (const float*)d_in[5];
    const float* O      = (const float*)d_in[6];

    float* out_scores = (float*)d_out;
    float* out_D      = (float*)d_out + (long long)BB * NT;

    dmspline_fused<<<BB + COPY_BLOCKS, THREADS>>>(
        x_vals, knots, ctx, tids, D, W, O, out_scores, out_D);
}